// round 1
// baseline (speedup 1.0000x reference)
#include <cuda_runtime.h>
#include <cstdint>

// ---------------------------------------------------------------------------
// Conv2d 3x3 pad1 stride1, NCHW, fp32 -> implicit GEMM with TF32 mma.sync.
//   M = Cout = 256, N = B*H*W = 100352, K = Cin*9 = 1152 (tap-major)
//   C[m,n] = sum_k Wt[k][m] * im2col[k][n]
// ---------------------------------------------------------------------------

#define B_IMG 32
#define CIN   128
#define COUT  256
#define HWDIM 56
#define PIX   (HWDIM*HWDIM)   // 3136
#define KTOT  (CIN*9)         // 1152
#define NPIX  (B_IMG*PIX)     // 100352

#define BM 128
#define BN 128
#define BK 16
#define NCHUNK (KTOT/BK)      // 72
#define LDA 136               // padded smem row stride (words) -> conflict-free frags

// Pre-transposed, tf32-converted weights: g_Wt[k*256 + m]
__device__ uint32_t g_Wt[KTOT * COUT];

__device__ __forceinline__ uint32_t f2tf(float v) {
    uint32_t r;
    asm("cvt.rna.tf32.f32 %0, %1;" : "=r"(r) : "f"(v));
    return r;
}

// W[m][c][kh][kw] -> g_Wt[(tap*128 + c)*256 + m], tap = kh*3+kw
__global__ void wt_transform_kernel(const float* __restrict__ W) {
    int idx = blockIdx.x * blockDim.x + threadIdx.x;
    if (idx >= KTOT * COUT) return;
    int m   = idx & (COUT - 1);
    int k   = idx >> 8;
    int tap = k >> 7;
    int c   = k & (CIN - 1);
    int kh  = tap / 3;
    int kw  = tap - kh * 3;
    g_Wt[idx] = f2tf(W[((m * CIN + c) * 3 + kh) * 3 + kw]);
}

__global__ __launch_bounds__(256, 2) void conv_mma_kernel(
    const float* __restrict__ x, float* __restrict__ out)
{
    __shared__ __align__(16) uint32_t As[2][BK][LDA];
    __shared__ __align__(16) uint32_t Bs[2][BK][LDA];

    const int tid  = threadIdx.x;
    const int lane = tid & 31;
    const int warp = tid >> 5;
    const int g    = lane >> 2;   // group id 0..7
    const int tig  = lane & 3;    // thread-in-group 0..3
    const int wm   = warp & 1;    // 2 warps along M
    const int wn   = warp >> 1;   // 4 warps along N

    const int m0 = blockIdx.y * BM;
    const int n0 = blockIdx.x * BN;

    // ---- B (im2col) load geometry: one pixel per thread, 8 k-rows ----
    const int nn    = tid & 127;
    const int grp   = tid >> 7;            // 0/1 -> even/odd k rows
    const int n     = n0 + nn;
    const int b     = n / PIX;
    const int hw    = n - b * PIX;
    const int h     = hw / HWDIM;
    const int w     = hw - h * HWDIM;
    const int xbase = b * (CIN * PIX);

    // ---- A load geometry: two uint4 per thread ----
    const int kkA = tid >> 5;              // 0..7 (second row is +8)
    const int mvA = (tid & 31) << 2;       // 0,4,...,124

    uint4    aReg0, aReg1;
    uint32_t bReg[8];

    float acc[4][4][4];
#pragma unroll
    for (int i = 0; i < 4; i++)
#pragma unroll
        for (int j = 0; j < 4; j++)
#pragma unroll
            for (int e = 0; e < 4; e++) acc[i][j][e] = 0.f;

    const uint4* WtV = reinterpret_cast<const uint4*>(g_Wt);

    auto loadChunk = [&](int t) {
        const int gk0 = t * BK;
        // A: [gk0..gk0+15] x [m0..m0+127], coalesced 16B per lane
        aReg0 = WtV[((gk0 + kkA    ) * COUT + m0 + mvA) >> 2];
        aReg1 = WtV[((gk0 + kkA + 8) * COUT + m0 + mvA) >> 2];
        // B: tap is constant within a 16-wide chunk (128 % 16 == 0)
        const int tap = gk0 >> 7;
        const int c0  = gk0 & (CIN - 1);
        const int kh  = tap / 3;
        const int kw  = tap - kh * 3;
        const int ih  = h + kh - 1;
        const int iw  = w + kw - 1;
        const bool valid = ((unsigned)ih < HWDIM) && ((unsigned)iw < HWDIM);
        const int off = xbase + ih * HWDIM + iw;
#pragma unroll
        for (int e = 0; e < 8; e++) {
            const int kk = grp + 2 * e;
            const int c  = c0 + kk;
            float v = valid ? __ldg(x + off + c * PIX) : 0.f;
            bReg[e] = f2tf(v);
        }
    };

    auto storeChunk = [&](int buf) {
        *reinterpret_cast<uint4*>(&As[buf][kkA    ][mvA]) = aReg0;
        *reinterpret_cast<uint4*>(&As[buf][kkA + 8][mvA]) = aReg1;
#pragma unroll
        for (int e = 0; e < 8; e++)
            Bs[buf][grp + 2 * e][nn] = bReg[e];
    };

    auto computeChunk = [&](int buf) {
#pragma unroll
        for (int ks = 0; ks < 2; ks++) {
            const int kb = ks * 8;
            uint32_t af[4][4];
            uint32_t bf[4][2];
#pragma unroll
            for (int i = 0; i < 4; i++) {
                const int rm = wm * 64 + i * 16 + g;
                af[i][0] = As[buf][kb + tig    ][rm    ];
                af[i][1] = As[buf][kb + tig    ][rm + 8];
                af[i][2] = As[buf][kb + tig + 4][rm    ];
                af[i][3] = As[buf][kb + tig + 4][rm + 8];
            }
#pragma unroll
            for (int j = 0; j < 4; j++) {
                const int cn = wn * 32 + j * 8 + g;
                bf[j][0] = Bs[buf][kb + tig    ][cn];
                bf[j][1] = Bs[buf][kb + tig + 4][cn];
            }
#pragma unroll
            for (int i = 0; i < 4; i++)
#pragma unroll
                for (int j = 0; j < 4; j++) {
                    asm volatile(
                        "mma.sync.aligned.m16n8k8.row.col.f32.tf32.tf32.f32 "
                        "{%0,%1,%2,%3}, {%4,%5,%6,%7}, {%8,%9}, {%0,%1,%2,%3};"
                        : "+f"(acc[i][j][0]), "+f"(acc[i][j][1]),
                          "+f"(acc[i][j][2]), "+f"(acc[i][j][3])
                        : "r"(af[i][0]), "r"(af[i][1]),
                          "r"(af[i][2]), "r"(af[i][3]),
                          "r"(bf[j][0]), "r"(bf[j][1]));
                }
        }
    };

    // ---- pipelined main loop (double-buffered smem, LDG prefetch) ----
    loadChunk(0);
    storeChunk(0);
    __syncthreads();

#pragma unroll 1
    for (int t = 0; t < NCHUNK; ++t) {
        if (t + 1 < NCHUNK) loadChunk(t + 1);   // issue LDGs early
        computeChunk(t & 1);
        __syncthreads();
        if (t + 1 < NCHUNK) {
            storeChunk((t + 1) & 1);
            __syncthreads();
        }
    }

    // ---- epilogue: scatter accumulators to NCHW output ----
#pragma unroll
    for (int j = 0; j < 4; j++) {
        const int cn = n0 + wn * 32 + j * 8 + tig * 2;
#pragma unroll
        for (int cc = 0; cc < 2; ++cc) {
            const int ncol = cn + cc;
            const int bb   = ncol / PIX;
            const int phw  = ncol - bb * PIX;
            float* obase = out + bb * (COUT * PIX) + phw;
#pragma unroll
            for (int i = 0; i < 4; i++) {
                const int r0 = m0 + wm * 64 + i * 16 + g;
                obase[(r0    ) * PIX] = acc[i][j][    cc];
                obase[(r0 + 8) * PIX] = acc[i][j][2 + cc];
            }
        }
    }
}

extern "C" void kernel_launch(void* const* d_in, const int* in_sizes, int n_in,
                              void* d_out, int out_size)
{
    const float* x = (const float*)d_in[0];
    const float* W = (const float*)d_in[1];
    // Defensive: metadata order should be (x, W); swap if W came first.
    if (n_in >= 2 && in_sizes[0] == KTOT * COUT) {
        const float* t = x; x = W; W = t;
    }

    wt_transform_kernel<<<(KTOT * COUT + 255) / 256, 256>>>(W);

    dim3 grid(NPIX / BN, COUT / BM);
    conv_mma_kernel<<<grid, 256>>>(x, (float*)d_out);
}

// round 2
// speedup vs baseline: 1.0011x; 1.0011x over previous
#include <cuda_runtime.h>
#include <cstdint>

// ---------------------------------------------------------------------------
// Conv2d 3x3 pad1 stride1, NCHW, fp32 -> implicit GEMM with TF32 mma.sync.
//   M = Cout = 256, N = B*H*W = 100352, K = Cin*9 = 1152 (tap-major)
//   C[m,n] = sum_k Wt[k][m] * im2col[k][n]
// ---------------------------------------------------------------------------

#define B_IMG 32
#define CIN   128
#define COUT  256
#define HWDIM 56
#define PIX   (HWDIM*HWDIM)   // 3136
#define KTOT  (CIN*9)         // 1152
#define NPIX  (B_IMG*PIX)     // 100352

#define BM 128
#define BN 128
#define BK 16
#define NCHUNK (KTOT/BK)      // 72
#define LDA 136               // padded smem row stride (words) -> conflict-free frags

// Pre-transposed, tf32-converted weights: g_Wt[k*256 + m]
__device__ uint32_t g_Wt[KTOT * COUT];

__device__ __forceinline__ uint32_t f2tf(float v) {
    uint32_t r;
    asm("cvt.rna.tf32.f32 %0, %1;" : "=r"(r) : "f"(v));
    return r;
}

// W[m][c][kh][kw] -> g_Wt[(tap*128 + c)*256 + m], tap = kh*3+kw
__global__ void wt_transform_kernel(const float* __restrict__ W) {
    int idx = blockIdx.x * blockDim.x + threadIdx.x;
    if (idx >= KTOT * COUT) return;
    int m   = idx & (COUT - 1);
    int k   = idx >> 8;
    int tap = k >> 7;
    int c   = k & (CIN - 1);
    int kh  = tap / 3;
    int kw  = tap - kh * 3;
    g_Wt[idx] = f2tf(W[((m * CIN + c) * 3 + kh) * 3 + kw]);
}

__global__ __launch_bounds__(256, 2) void conv_mma_kernel(
    const float* __restrict__ x, float* __restrict__ out)
{
    __shared__ __align__(16) uint32_t As[2][BK][LDA];
    __shared__ __align__(16) uint32_t Bs[2][BK][LDA];

    const int tid  = threadIdx.x;
    const int lane = tid & 31;
    const int warp = tid >> 5;
    const int g    = lane >> 2;   // group id 0..7
    const int tig  = lane & 3;    // thread-in-group 0..3
    const int wm   = warp & 1;    // 2 warps along M
    const int wn   = warp >> 1;   // 4 warps along N

    const int m0 = blockIdx.y * BM;
    const int n0 = blockIdx.x * BN;

    // ---- B (im2col) load geometry: one pixel per thread, 8 k-rows ----
    const int nn    = tid & 127;
    const int grp   = tid >> 7;            // 0/1 -> even/odd k rows
    const int n     = n0 + nn;
    const int b     = n / PIX;
    const int hw    = n - b * PIX;
    const int h     = hw / HWDIM;
    const int w     = hw - h * HWDIM;
    const int xbase = b * (CIN * PIX);

    // ---- A load geometry: two uint4 per thread ----
    const int kkA = tid >> 5;              // 0..7 (second row is +8)
    const int mvA = (tid & 31) << 2;       // 0,4,...,124

    uint4    aReg0, aReg1;
    uint32_t bReg[8];

    float acc[4][4][4];
#pragma unroll
    for (int i = 0; i < 4; i++)
#pragma unroll
        for (int j = 0; j < 4; j++)
#pragma unroll
            for (int e = 0; e < 4; e++) acc[i][j][e] = 0.f;

    const uint4* WtV = reinterpret_cast<const uint4*>(g_Wt);

    auto loadChunk = [&](int t) {
        const int gk0 = t * BK;
        // A: [gk0..gk0+15] x [m0..m0+127], coalesced 16B per lane
        aReg0 = WtV[((gk0 + kkA    ) * COUT + m0 + mvA) >> 2];
        aReg1 = WtV[((gk0 + kkA + 8) * COUT + m0 + mvA) >> 2];
        // B: tap is constant within a 16-wide chunk (128 % 16 == 0)
        const int tap = gk0 >> 7;
        const int c0  = gk0 & (CIN - 1);
        const int kh  = tap / 3;
        const int kw  = tap - kh * 3;
        const int ih  = h + kh - 1;
        const int iw  = w + kw - 1;
        const bool valid = ((unsigned)ih < HWDIM) && ((unsigned)iw < HWDIM);
        const int off = xbase + ih * HWDIM + iw;
#pragma unroll
        for (int e = 0; e < 8; e++) {
            const int kk = grp + 2 * e;
            const int c  = c0 + kk;
            float v = valid ? __ldg(x + off + c * PIX) : 0.f;
            bReg[e] = f2tf(v);
        }
    };

    auto storeChunk = [&](int buf) {
        *reinterpret_cast<uint4*>(&As[buf][kkA    ][mvA]) = aReg0;
        *reinterpret_cast<uint4*>(&As[buf][kkA + 8][mvA]) = aReg1;
#pragma unroll
        for (int e = 0; e < 8; e++)
            Bs[buf][grp + 2 * e][nn] = bReg[e];
    };

    auto computeChunk = [&](int buf) {
#pragma unroll
        for (int ks = 0; ks < 2; ks++) {
            const int kb = ks * 8;
            uint32_t af[4][4];
            uint32_t bf[4][2];
#pragma unroll
            for (int i = 0; i < 4; i++) {
                const int rm = wm * 64 + i * 16 + g;
                af[i][0] = As[buf][kb + tig    ][rm    ];
                af[i][1] = As[buf][kb + tig    ][rm + 8];
                af[i][2] = As[buf][kb + tig + 4][rm    ];
                af[i][3] = As[buf][kb + tig + 4][rm + 8];
            }
#pragma unroll
            for (int j = 0; j < 4; j++) {
                const int cn = wn * 32 + j * 8 + g;
                bf[j][0] = Bs[buf][kb + tig    ][cn];
                bf[j][1] = Bs[buf][kb + tig + 4][cn];
            }
#pragma unroll
            for (int i = 0; i < 4; i++)
#pragma unroll
                for (int j = 0; j < 4; j++) {
                    asm volatile(
                        "mma.sync.aligned.m16n8k8.row.col.f32.tf32.tf32.f32 "
                        "{%0,%1,%2,%3}, {%4,%5,%6,%7}, {%8,%9}, {%0,%1,%2,%3};"
                        : "+f"(acc[i][j][0]), "+f"(acc[i][j][1]),
                          "+f"(acc[i][j][2]), "+f"(acc[i][j][3])
                        : "r"(af[i][0]), "r"(af[i][1]),
                          "r"(af[i][2]), "r"(af[i][3]),
                          "r"(bf[j][0]), "r"(bf[j][1]));
                }
        }
    };

    // ---- pipelined main loop (double-buffered smem, LDG prefetch) ----
    loadChunk(0);
    storeChunk(0);
    __syncthreads();

#pragma unroll 1
    for (int t = 0; t < NCHUNK; ++t) {
        if (t + 1 < NCHUNK) loadChunk(t + 1);   // issue LDGs early
        computeChunk(t & 1);
        __syncthreads();
        if (t + 1 < NCHUNK) {
            storeChunk((t + 1) & 1);
            __syncthreads();
        }
    }

    // ---- epilogue: scatter accumulators to NCHW output ----
#pragma unroll
    for (int j = 0; j < 4; j++) {
        const int cn = n0 + wn * 32 + j * 8 + tig * 2;
#pragma unroll
        for (int cc = 0; cc < 2; ++cc) {
            const int ncol = cn + cc;
            const int bb   = ncol / PIX;
            const int phw  = ncol - bb * PIX;
            float* obase = out + bb * (COUT * PIX) + phw;
#pragma unroll
            for (int i = 0; i < 4; i++) {
                const int r0 = m0 + wm * 64 + i * 16 + g;
                obase[(r0    ) * PIX] = acc[i][j][    cc];
                obase[(r0 + 8) * PIX] = acc[i][j][2 + cc];
            }
        }
    }
}

extern "C" void kernel_launch(void* const* d_in, const int* in_sizes, int n_in,
                              void* d_out, int out_size)
{
    const float* x = (const float*)d_in[0];
    const float* W = (const float*)d_in[1];
    // Defensive: metadata order should be (x, W); swap if W came first.
    if (n_in >= 2 && in_sizes[0] == KTOT * COUT) {
        const float* t = x; x = W; W = t;
    }

    wt_transform_kernel<<<(KTOT * COUT + 255) / 256, 256>>>(W);

    dim3 grid(NPIX / BN, COUT / BM);
    conv_mma_kernel<<<grid, 256>>>(x, (float*)d_out);
}

// round 4
// speedup vs baseline: 1.3707x; 1.3692x over previous
#include <cuda_runtime.h>
#include <cuda.h>
#include <cstdint>

#define CIN   128
#define COUT  256
#define HW    56
#define HP    58
#define PIX   (HW*HW)
#define KTOT  1152
#define NB    32

#define TILE_H   4
#define BM       128
#define A_BYTES  16384            // 128 m x 32 k x 4B
#define B_BYTES  44544            // 348 rows x 128B (6x58 halo)
#define B_STRIDE 45056            // 1024-aligned
#define SMEM_TOTAL (1024 + 3*A_BYTES + 2*B_STRIDE)   // 140288

__device__ uint32_t g_Wt[COUT * KTOT];          // [m][k], tf32 bits
__device__ uint32_t g_xp[NB * HP * HP * CIN];   // [b][hp][wp][c], tf32 bits

__device__ __forceinline__ uint32_t smem_u32(const void* p) {
    uint32_t a;
    asm("{ .reg .u64 t; cvta.to.shared.u64 t, %1; cvt.u32.u64 %0, t; }" : "=r"(a) : "l"(p));
    return a;
}
__device__ __forceinline__ uint32_t f2tf(float v) {
    uint32_t r; asm("cvt.rna.tf32.f32 %0, %1;" : "=r"(r) : "f"(v)); return r;
}

#define MBAR_INIT(a, c) asm volatile("mbarrier.init.shared.b64 [%0], %1;" :: "r"(a), "r"(c) : "memory")
#define MBAR_TX(a, b)   asm volatile("mbarrier.arrive.expect_tx.shared.b64 _, [%0], %1;" :: "r"(a), "r"(b) : "memory")
#define MBAR_ARRIVE(a)  asm volatile("mbarrier.arrive.shared.b64 _, [%0];" :: "r"(a) : "memory")
#define MBAR_WAIT(a, p) do {                                                    \
    uint32_t _m = (a), _p = (p), _d;                                            \
    asm volatile("{\n\t.reg .pred q;\n\t"                                       \
        "mbarrier.try_wait.parity.acquire.cta.shared::cta.b64 q, [%1], %2;\n\t" \
        "selp.b32 %0, 1, 0, q;\n\t}" : "=r"(_d) : "r"(_m), "r"(_p) : "memory"); \
    if (!_d) {                                                                  \
        asm volatile("{\n\t.reg .pred Q;\n\t"                                   \
        "WL_%=:\n\t"                                                            \
        "mbarrier.try_wait.parity.acquire.cta.shared::cta.b64 Q, [%0], %1, 0x989680;\n\t" \
        "@Q bra.uni WD_%=;\n\t"                                                 \
        "bra.uni WL_%=;\n\t"                                                    \
        "WD_%=:\n\t}" :: "r"(_m), "r"(_p) : "memory");                          \
    } } while (0)

#define TMA_2D(d, tm, c0, c1, mb)                                               \
    asm volatile("cp.async.bulk.tensor.2d.shared::cta.global.tile.mbarrier::complete_tx::bytes " \
        "[%0], [%1, {%2, %3}], [%4];" :: "r"(d), "l"(tm), "r"(c0), "r"(c1), "r"(mb) : "memory")
#define TMA_4D(d, tm, c0, c1, c2, c3, mb)                                       \
    asm volatile("cp.async.bulk.tensor.4d.shared::cta.global.tile.mbarrier::complete_tx::bytes " \
        "[%0], [%1, {%2, %3, %4, %5}], [%6];" :: "r"(d), "l"(tm), "r"(c0), "r"(c1), "r"(c2), "r"(c3), "r"(mb) : "memory")

// ---- prepass: W[m][c][dh][dw] -> g_Wt[m*1152 + (dh*3+dw)*128 + c]
__global__ void wt_kernel(const float* __restrict__ W) {
    int idx = blockIdx.x * blockDim.x + threadIdx.x;
    if (idx >= COUT * KTOT) return;
    int m = idx / KTOT, k = idx - m * KTOT;
    int tap = k >> 7, c = k & 127, dh = tap / 3, dw = tap - dh * 3;
    g_Wt[idx] = f2tf(W[((m * CIN + c) * 3 + dh) * 3 + dw]);
}
// ---- prepass: x[b][c][h][w] -> g_xp[b][h+1][w+1][c] (tf32, interior)
__global__ void xpad_kernel(const float* __restrict__ x) {
    __shared__ float sm[CIN * 57];
    int bx = blockIdx.x, b = bx / HW, h = bx - b * HW, tid = threadIdx.x;
    const float* xb = x + ((size_t)b * CIN) * PIX + h * HW;
    for (int i = tid; i < CIN * HW; i += 256) {
        int c = i / HW, w = i - c * HW;
        sm[c * 57 + w] = xb[c * PIX + w];
    }
    __syncthreads();
    uint32_t* xr = g_xp + ((size_t)(b * HP + h + 1)) * HP * CIN;
    for (int i = tid; i < HW * CIN; i += 256) {
        int w = i >> 7, c = i & 127;
        xr[(w + 1) * CIN + c] = f2tf(sm[c * 57 + w]);
    }
}
// ---- prepass: zero padded borders of g_xp
__global__ void xborder_kernel() {
    int idx = blockIdx.x * blockDim.x + threadIdx.x;
    if (idx >= NB * 228 * CIN) return;
    int c = idx & 127, r = idx >> 7, b = r / 228, cc = r - b * 228;
    int hp, wp;
    if (cc < 58)       { hp = 0;        wp = cc; }
    else if (cc < 116) { hp = 57;       wp = cc - 58; }
    else if (cc < 172) { hp = cc - 115; wp = 0; }
    else               { hp = cc - 171; wp = 57; }
    g_xp[((b * HP + hp) * HP + wp) * CIN + c] = 0u;
}

// ============================================================================
// Main: TMA-fed mma.sync tf32 implicit GEMM with halo B reuse.
//   CTA: M=128 (blockIdx.z half), N=224 (4 h-rows x 56 w), K = 4 cchunks x 9 taps
//   smem: barriers | A[3][16KB] | B[2][45KB(6x58 halo, 32c)]
// ============================================================================
__global__ void __launch_bounds__(256, 1) conv_tc(
    const __grid_constant__ CUtensorMap tma_a,
    const __grid_constant__ CUtensorMap tma_b,
    float* __restrict__ out)
{
    extern __shared__ __align__(1024) uint8_t smem[];
    const uint32_t sb0 = smem_u32(smem);
    uint32_t* const smw = reinterpret_cast<uint32_t*>(smem);

    const int tid  = threadIdx.x;
    const int lane = tid & 31;
    const int g    = lane >> 2;          // 0..7
    const int tig  = lane & 3;           // 0..3
    const int warp = tid >> 5;
    const int wm   = warp >> 2;          // 0..1 (m half of CTA tile)
    const int wn   = warp & 3;           // 0..3 (h row)

    const int h0 = blockIdx.x * TILE_H;
    const int b  = blockIdx.y;
    const int m0 = blockIdx.z * BM;

    // barriers: afull[3]@0, aempty[3]@24, bfull[2]@48, bempty[2]@64
    if (tid == 0) {
        for (int s = 0; s < 3; s++) { MBAR_INIT(sb0 + 8*s, 1); MBAR_INIT(sb0 + 24 + 8*s, 8); }
        for (int s = 0; s < 2; s++) { MBAR_INIT(sb0 + 48 + 8*s, 1); MBAR_INIT(sb0 + 64 + 8*s, 8); }
    }
    __syncthreads();

    // prologue TMAs: A chunks 0,1 and B chunk 0
    if (tid == 0) {
        // chunk u -> cc=u/9, tap=u%9, k0 = tap*128 + cc*32
        MBAR_TX(sb0 + 0, A_BYTES);
        TMA_2D(sb0 + 1024, &tma_a, 0, m0, sb0 + 0);               // u=0: tap0 cc0 k0=0
        MBAR_TX(sb0 + 8, A_BYTES);
        TMA_2D(sb0 + 1024 + A_BYTES, &tma_a, 128, m0, sb0 + 8);   // u=1: tap1 k0=128
        MBAR_TX(sb0 + 48, B_BYTES);
        TMA_4D(sb0 + 1024 + 3*A_BYTES, &tma_b, 0, 0, h0, b, sb0 + 48);  // cchunk 0
    }

    float acc[4][7][4];
#pragma unroll
    for (int i = 0; i < 4; i++)
#pragma unroll
        for (int j = 0; j < 7; j++)
#pragma unroll
            for (int e = 0; e < 4; e++) acc[i][j][e] = 0.f;

    const int abase = (wm * 64 + g) * 32;   // + i*512 per m-tile
    const int ma    = 4 * g;                // A swizzle xor (m&7 == g)

    for (int cc = 0; cc < 4; cc++) {
        if (tid == 0 && cc + 1 < 4) {       // prefetch next B halo
            const int u = cc + 1, s = u & 1;
            MBAR_WAIT(sb0 + 64 + 8*s, (u == 1) ? 1 : 0);
            MBAR_TX(sb0 + 48 + 8*s, B_BYTES);
            TMA_4D(sb0 + 1024 + 3*A_BYTES + s*B_STRIDE, &tma_b, u*32, 0, h0, b, sb0 + 48 + 8*s);
        }
        MBAR_WAIT(sb0 + 48 + 8*(cc & 1), (cc >> 1) & 1);
        const uint32_t* Bb = smw + 256 + 3*(A_BYTES/4) + (cc & 1)*(B_STRIDE/4);

        for (int tap = 0; tap < 9; tap++) {
            const int t = cc * 9 + tap;
            if (tid == 0 && t + 2 < 36) {    // prefetch A chunk t+2
                const int u = t + 2, s = u % 3;
                const int ucc = u / 9, utap = u - ucc * 9;
                MBAR_WAIT(sb0 + 24 + 8*s, 1 ^ ((u / 3) & 1));
                MBAR_TX(sb0 + 8*s, A_BYTES);
                TMA_2D(sb0 + 1024 + s*A_BYTES, &tma_a, utap*128 + ucc*32, m0, sb0 + 8*s);
            }
            const int sA = t % 3;
            MBAR_WAIT(sb0 + 8*sA, (t / 3) & 1);
            const uint32_t* Ab = smw + 256 + sA * (A_BYTES/4);

            const int dh = tap / 3, dw = tap - dh * 3;
            const int rb2 = (wn + dh) * 58 + dw + g;   // B halo row for this lane
            const int mb  = 4 * (rb2 & 7);             // B swizzle xor

#pragma unroll
            for (int ks = 0; ks < 4; ks++) {
                const int kb = 8 * ks;
                const int kA0 = (kb + tig) ^ ma, kA1 = (kb + tig + 4) ^ ma;
                const int kB0 = (kb + tig) ^ mb, kB1 = (kb + tig + 4) ^ mb;
                uint32_t af[4][4], bf[7][2];
#pragma unroll
                for (int i = 0; i < 4; i++) {
                    const int ar = abase + i * 512;
                    af[i][0] = Ab[ar +       kA0];
                    af[i][1] = Ab[ar + 256 + kA0];
                    af[i][2] = Ab[ar +       kA1];
                    af[i][3] = Ab[ar + 256 + kA1];
                }
#pragma unroll
                for (int j = 0; j < 7; j++) {
                    const int br = (rb2 + 8 * j) * 32;
                    bf[j][0] = Bb[br + kB0];
                    bf[j][1] = Bb[br + kB1];
                }
#pragma unroll
                for (int i = 0; i < 4; i++)
#pragma unroll
                    for (int j = 0; j < 7; j++) {
                        asm volatile(
                            "mma.sync.aligned.m16n8k8.row.col.f32.tf32.tf32.f32 "
                            "{%0,%1,%2,%3}, {%4,%5,%6,%7}, {%8,%9}, {%0,%1,%2,%3};"
                            : "+f"(acc[i][j][0]), "+f"(acc[i][j][1]),
                              "+f"(acc[i][j][2]), "+f"(acc[i][j][3])
                            : "r"(af[i][0]), "r"(af[i][1]),
                              "r"(af[i][2]), "r"(af[i][3]),
                              "r"(bf[j][0]), "r"(bf[j][1]));
                    }
            }
            if (lane == 0) MBAR_ARRIVE(sb0 + 24 + 8*sA);   // A stage consumed
        }
        if (lane == 0) MBAR_ARRIVE(sb0 + 64 + 8*(cc & 1)); // B chunk consumed
    }

    // ---- epilogue: acc -> out[b][m][h0+wn][w] ----
    const int h = h0 + wn;
#pragma unroll
    for (int i = 0; i < 4; i++) {
        const int m = m0 + wm * 64 + i * 16 + g;
        float* o0 = out + (((size_t)b * COUT + m    ) * PIX) + h * HW;
        float* o1 = out + (((size_t)b * COUT + m + 8) * PIX) + h * HW;
#pragma unroll
        for (int j = 0; j < 7; j++) {
            const int w = j * 8 + tig * 2;
            *reinterpret_cast<float2*>(o0 + w) = make_float2(acc[i][j][0], acc[i][j][1]);
            *reinterpret_cast<float2*>(o1 + w) = make_float2(acc[i][j][2], acc[i][j][3]);
        }
    }
}

extern "C" void kernel_launch(void* const* d_in, const int* in_sizes, int n_in,
                              void* d_out, int out_size)
{
    const float* x = (const float*)d_in[0];
    const float* W = (const float*)d_in[1];
    if (n_in >= 2 && in_sizes[0] == COUT * CIN * 9) { const float* t = x; x = W; W = t; }

    typedef CUresult (*EncodeFn)(CUtensorMap*, CUtensorMapDataType, cuuint32_t, void*,
                                 const cuuint64_t*, const cuuint64_t*, const cuuint32_t*,
                                 const cuuint32_t*, CUtensorMapInterleave, CUtensorMapSwizzle,
                                 CUtensorMapL2promotion, CUtensorMapFloatOOBfill);
    void* fnp = nullptr;
    cudaDriverEntryPointQueryResult qr;
    cudaGetDriverEntryPoint("cuTensorMapEncodeTiled", &fnp, cudaEnableDefault, &qr);
    EncodeFn encode = (EncodeFn)fnp;

    void *wt_ptr, *xp_ptr;
    cudaGetSymbolAddress(&wt_ptr, g_Wt);
    cudaGetSymbolAddress(&xp_ptr, g_xp);

    CUtensorMap tma_a{}, tma_b{};
    {   // A: g_Wt [m=256][k=1152]; box [32 k, 128 m], SW128
        cuuint64_t dims[2]    = {KTOT, COUT};
        cuuint64_t strides[1] = {KTOT * 4};
        cuuint32_t box[2]     = {32, 128};
        cuuint32_t es[2]      = {1, 1};
        encode(&tma_a, CU_TENSOR_MAP_DATA_TYPE_FLOAT32, 2, wt_ptr, dims, strides, box, es,
               CU_TENSOR_MAP_INTERLEAVE_NONE, CU_TENSOR_MAP_SWIZZLE_128B,
               CU_TENSOR_MAP_L2_PROMOTION_L2_128B, CU_TENSOR_MAP_FLOAT_OOB_FILL_NONE);
    }
    {   // B: g_xp [b=32][hp=58][wp=58][c=128]; halo box [32 c, 58 w, 6 h, 1], SW128
        cuuint64_t dims[4]    = {CIN, HP, HP, NB};
        cuuint64_t strides[3] = {CIN * 4, (cuuint64_t)HP * CIN * 4, (cuuint64_t)HP * HP * CIN * 4};
        cuuint32_t box[4]     = {32, 58, 6, 1};
        cuuint32_t es[4]      = {1, 1, 1, 1};
        encode(&tma_b, CU_TENSOR_MAP_DATA_TYPE_FLOAT32, 4, xp_ptr, dims, strides, box, es,
               CU_TENSOR_MAP_INTERLEAVE_NONE, CU_TENSOR_MAP_SWIZZLE_128B,
               CU_TENSOR_MAP_L2_PROMOTION_L2_128B, CU_TENSOR_MAP_FLOAT_OOB_FILL_NONE);
    }

    wt_kernel<<<(COUT * KTOT + 255) / 256, 256>>>(W);
    xpad_kernel<<<NB * HW, 256>>>(x);
    xborder_kernel<<<(NB * 228 * CIN + 255) / 256, 256>>>();

    cudaFuncSetAttribute(conv_tc, cudaFuncAttributeMaxDynamicSharedMemorySize, SMEM_TOTAL);
    dim3 grid(14, 32, 2);
    conv_tc<<<grid, 256, SMEM_TOTAL>>>(tma_a, tma_b, (float*)d_out);
}

// round 6
// speedup vs baseline: 1.4607x; 1.0657x over previous
#include <cuda_runtime.h>
#include <cuda.h>
#include <cstdint>

#define CIN   128
#define COUT  256
#define HW    56
#define HP    58
#define PIX   (HW*HW)
#define KTOT  1152
#define NB    32

#define TILE_H   4
#define BM       128
#define A_BYTES  16384            // one packed chunk: 128 rows x 128B
#define B_BYTES  44544            // 348 rows x 128B (6x58 halo)
#define B_STRIDE 45056            // 1024-aligned
#define SMEM_TOTAL (1024 + 3*A_BYTES + 2*B_STRIDE)   // 140288

// g_Wt: fragment-packed weights, 72 chunks (t=0..35, z=0..1) x 4096 words.
// word idx: ((((chunk)*4 + ks)*8 + i8)*32 + lane)*4 + w
__device__ uint32_t g_Wt[COUT * KTOT];
__device__ uint32_t g_xp[NB * HP * HP * CIN];   // [b][hp][wp][c], tf32 bits

__device__ __forceinline__ uint32_t smem_u32(const void* p) {
    uint32_t a;
    asm("{ .reg .u64 t; cvta.to.shared.u64 t, %1; cvt.u32.u64 %0, t; }" : "=r"(a) : "l"(p));
    return a;
}
__device__ __forceinline__ uint32_t f2tf(float v) {
    uint32_t r; asm("cvt.rna.tf32.f32 %0, %1;" : "=r"(r) : "f"(v)); return r;
}

#define MBAR_INIT(a, c) asm volatile("mbarrier.init.shared.b64 [%0], %1;" :: "r"(a), "r"(c) : "memory")
#define MBAR_TX(a, b)   asm volatile("mbarrier.arrive.expect_tx.shared.b64 _, [%0], %1;" :: "r"(a), "r"(b) : "memory")
#define MBAR_ARRIVE(a)  asm volatile("mbarrier.arrive.shared.b64 _, [%0];" :: "r"(a) : "memory")
#define MBAR_WAIT(a, p) do {                                                    \
    uint32_t _m = (a), _p = (p), _d;                                            \
    asm volatile("{\n\t.reg .pred q;\n\t"                                       \
        "mbarrier.try_wait.parity.acquire.cta.shared::cta.b64 q, [%1], %2;\n\t" \
        "selp.b32 %0, 1, 0, q;\n\t}" : "=r"(_d) : "r"(_m), "r"(_p) : "memory"); \
    if (!_d) {                                                                  \
        asm volatile("{\n\t.reg .pred Q;\n\t"                                   \
        "WL_%=:\n\t"                                                            \
        "mbarrier.try_wait.parity.acquire.cta.shared::cta.b64 Q, [%0], %1, 0x989680;\n\t" \
        "@Q bra.uni WD_%=;\n\t"                                                 \
        "bra.uni WL_%=;\n\t"                                                    \
        "WD_%=:\n\t}" :: "r"(_m), "r"(_p) : "memory");                          \
    } } while (0)

#define TMA_2D(d, tm, c0, c1, mb)                                               \
    asm volatile("cp.async.bulk.tensor.2d.shared::cta.global.tile.mbarrier::complete_tx::bytes " \
        "[%0], [%1, {%2, %3}], [%4];" :: "r"(d), "l"(tm), "r"(c0), "r"(c1), "r"(mb) : "memory")
#define TMA_4D(d, tm, c0, c1, c2, c3, mb)                                       \
    asm volatile("cp.async.bulk.tensor.4d.shared::cta.global.tile.mbarrier::complete_tx::bytes " \
        "[%0], [%1, {%2, %3, %4, %5}], [%6];" :: "r"(d), "l"(tm), "r"(c0), "r"(c1), "r"(c2), "r"(c3), "r"(mb) : "memory")

// ---- prepass: W -> fragment-packed g_Wt ----
// chunk = t*2 + z; t = cc*9 + tap; k = tap*128 + cc*32 + kk
// m = z*128 + i8*16 + g + (w&1)*8 ; kk = ks*8 + tig + ((w>>1)&1)*4
__global__ void wt_kernel(const float* __restrict__ W) {
    int idx = blockIdx.x * blockDim.x + threadIdx.x;
    if (idx >= COUT * KTOT) return;
    int w     = idx & 3;
    int lane  = (idx >> 2) & 31;
    int i8    = (idx >> 7) & 7;
    int ks    = (idx >> 10) & 3;
    int chunk = idx >> 12;
    int z = chunk & 1, t = chunk >> 1;
    int cc = t / 9, tap = t - cc * 9;
    int g = lane >> 2, tig = lane & 3;
    int m  = z * 128 + i8 * 16 + g + (w & 1) * 8;
    int kk = ks * 8 + tig + ((w >> 1) & 1) * 4;
    int c  = cc * 32 + kk;
    int dh = tap / 3, dw = tap - dh * 3;
    g_Wt[idx] = f2tf(W[((m * CIN + c) * 3 + dh) * 3 + dw]);
}
// ---- prepass: x[b][c][h][w] -> g_xp[b][h+1][w+1][c] (tf32, interior)
__global__ void xpad_kernel(const float* __restrict__ x) {
    __shared__ float sm[CIN * 57];
    int bx = blockIdx.x, b = bx / HW, h = bx - b * HW, tid = threadIdx.x;
    const float* xb = x + ((size_t)b * CIN) * PIX + h * HW;
    for (int i = tid; i < CIN * HW; i += 256) {
        int c = i / HW, w = i - c * HW;
        sm[c * 57 + w] = xb[c * PIX + w];
    }
    __syncthreads();
    uint32_t* xr = g_xp + ((size_t)(b * HP + h + 1)) * HP * CIN;
    for (int i = tid; i < HW * CIN; i += 256) {
        int w = i >> 7, c = i & 127;
        xr[(w + 1) * CIN + c] = f2tf(sm[c * 57 + w]);
    }
}
// ---- prepass: zero padded borders of g_xp
__global__ void xborder_kernel() {
    int idx = blockIdx.x * blockDim.x + threadIdx.x;
    if (idx >= NB * 228 * CIN) return;
    int c = idx & 127, r = idx >> 7, b = r / 228, cc = r - b * 228;
    int hp, wp;
    if (cc < 58)       { hp = 0;        wp = cc; }
    else if (cc < 116) { hp = 57;       wp = cc - 58; }
    else if (cc < 172) { hp = cc - 115; wp = 0; }
    else               { hp = cc - 171; wp = 57; }
    g_xp[((b * HP + hp) * HP + wp) * CIN + c] = 0u;
}

// ============================================================================
// Main: TMA-fed mma.sync tf32, fragment-packed A (LDS.128), sw-pipelined frags.
//   CTA: M=128 (blockIdx.z half), N=224 (4 h-rows x 56 w), K = 4 cchunks x 9 taps
// ============================================================================
__global__ void __launch_bounds__(256, 1) conv_tc(
    const __grid_constant__ CUtensorMap tma_a,
    const __grid_constant__ CUtensorMap tma_b,
    float* __restrict__ out)
{
    extern __shared__ __align__(1024) uint8_t smem[];
    const uint32_t sb0 = smem_u32(smem);
    uint32_t* const smw = reinterpret_cast<uint32_t*>(smem);

    const int tid  = threadIdx.x;
    const int lane = tid & 31;
    const int g    = lane >> 2;
    const int tig  = lane & 3;
    const int warp = tid >> 5;
    const int wm   = warp >> 2;          // 0..1
    const int wn   = warp & 3;           // 0..3

    const int h0 = blockIdx.x * TILE_H;
    const int b  = blockIdx.y;
    const int z  = blockIdx.z;           // m half

    // barriers: afull[3]@0, aempty[3]@24, bfull[2]@48, bempty[2]@64
    if (tid == 0) {
        for (int s = 0; s < 3; s++) { MBAR_INIT(sb0 + 8*s, 1); MBAR_INIT(sb0 + 24 + 8*s, 8); }
        for (int s = 0; s < 2; s++) { MBAR_INIT(sb0 + 48 + 8*s, 1); MBAR_INIT(sb0 + 64 + 8*s, 8); }
    }
    __syncthreads();

    if (tid == 0) {   // prologue: A chunks 0,1 ; B chunk 0
        MBAR_TX(sb0 + 0, A_BYTES);
        TMA_2D(sb0 + 1024, &tma_a, 0, (0*2 + z) * 128, sb0 + 0);
        MBAR_TX(sb0 + 8, A_BYTES);
        TMA_2D(sb0 + 1024 + A_BYTES, &tma_a, 0, (1*2 + z) * 128, sb0 + 8);
        MBAR_TX(sb0 + 48, B_BYTES);
        TMA_4D(sb0 + 1024 + 3*A_BYTES, &tma_b, 0, 0, h0, b, sb0 + 48);
    }

    float acc[4][7][4];
#pragma unroll
    for (int i = 0; i < 4; i++)
#pragma unroll
        for (int j = 0; j < 7; j++)
#pragma unroll
            for (int e = 0; e < 4; e++) acc[i][j][e] = 0.f;

    uint4    af[2][4];
    uint32_t bf[2][7][2];

    for (int cc = 0; cc < 4; cc++) {
        if (tid == 0 && cc + 1 < 4) {       // prefetch next B halo
            const int u = cc + 1, s = u & 1;
            MBAR_WAIT(sb0 + 64 + 8*s, (u == 1) ? 1 : 0);
            MBAR_TX(sb0 + 48 + 8*s, B_BYTES);
            TMA_4D(sb0 + 1024 + 3*A_BYTES + s*B_STRIDE, &tma_b, u*32, 0, h0, b, sb0 + 48 + 8*s);
        }
        MBAR_WAIT(sb0 + 48 + 8*(cc & 1), (cc >> 1) & 1);
        const uint32_t* Bb = smw + 256 + 3*(A_BYTES/4) + (cc & 1)*(B_STRIDE/4);

        for (int tap = 0; tap < 9; tap++) {
            const int t = cc * 9 + tap;
            if (tid == 0 && t + 2 < 36) {    // prefetch A chunk t+2
                const int u = t + 2, s = u % 3;
                MBAR_WAIT(sb0 + 24 + 8*s, 1 ^ ((u / 3) & 1));
                MBAR_TX(sb0 + 8*s, A_BYTES);
                TMA_2D(sb0 + 1024 + s*A_BYTES, &tma_a, 0, (u*2 + z) * 128, sb0 + 8*s);
            }
            const int sA = t % 3;
            MBAR_WAIT(sb0 + 8*sA, (t / 3) & 1);
            const uint4* A4 = reinterpret_cast<const uint4*>(smw + 256 + sA * (A_BYTES/4));

            const int dh = tap / 3, dw = tap - dh * 3;
            const int rb2 = (wn + dh) * 58 + dw + g;   // B halo row for this lane
            const int mb  = 4 * (rb2 & 7);             // B swizzle xor

            auto loadFrags = [&](int ks, int pb) {
#pragma unroll
                for (int i = 0; i < 4; i++)
                    af[pb][i] = A4[(ks * 8 + wm * 4 + i) * 32 + lane];
                const int kb = 8 * ks;
                const int kB0 = (kb + tig) ^ mb, kB1 = (kb + tig + 4) ^ mb;
#pragma unroll
                for (int j = 0; j < 7; j++) {
                    const int br = (rb2 + 8 * j) * 32;
                    bf[pb][j][0] = Bb[br + kB0];
                    bf[pb][j][1] = Bb[br + kB1];
                }
            };

            loadFrags(0, 0);
#pragma unroll
            for (int ks = 0; ks < 4; ks++) {
                if (ks < 3) loadFrags(ks + 1, (ks + 1) & 1);
                const int pb = ks & 1;
#pragma unroll
                for (int i = 0; i < 4; i++)
#pragma unroll
                    for (int j = 0; j < 7; j++) {
                        asm volatile(
                            "mma.sync.aligned.m16n8k8.row.col.f32.tf32.tf32.f32 "
                            "{%0,%1,%2,%3}, {%4,%5,%6,%7}, {%8,%9}, {%0,%1,%2,%3};"
                            : "+f"(acc[i][j][0]), "+f"(acc[i][j][1]),
                              "+f"(acc[i][j][2]), "+f"(acc[i][j][3])
                            : "r"(af[pb][i].x), "r"(af[pb][i].y),
                              "r"(af[pb][i].z), "r"(af[pb][i].w),
                              "r"(bf[pb][j][0]), "r"(bf[pb][j][1]));
                    }
            }
            if (lane == 0) MBAR_ARRIVE(sb0 + 24 + 8*sA);   // A stage consumed
        }
        if (lane == 0) MBAR_ARRIVE(sb0 + 64 + 8*(cc & 1)); // B chunk consumed
    }

    // ---- epilogue: acc -> out[b][m][h0+wn][w] ----
    const int h = h0 + wn;
#pragma unroll
    for (int i = 0; i < 4; i++) {
        const int m = z * BM + wm * 64 + i * 16 + g;
        float* o0 = out + (((size_t)b * COUT + m    ) * PIX) + h * HW;
        float* o1 = out + (((size_t)b * COUT + m + 8) * PIX) + h * HW;
#pragma unroll
        for (int j = 0; j < 7; j++) {
            const int w = j * 8 + tig * 2;
            *reinterpret_cast<float2*>(o0 + w) = make_float2(acc[i][j][0], acc[i][j][1]);
            *reinterpret_cast<float2*>(o1 + w) = make_float2(acc[i][j][2], acc[i][j][3]);
        }
    }
}

extern "C" void kernel_launch(void* const* d_in, const int* in_sizes, int n_in,
                              void* d_out, int out_size)
{
    const float* x = (const float*)d_in[0];
    const float* W = (const float*)d_in[1];
    if (n_in >= 2 && in_sizes[0] == COUT * CIN * 9) { const float* t = x; x = W; W = t; }

    typedef CUresult (*EncodeFn)(CUtensorMap*, CUtensorMapDataType, cuuint32_t, void*,
                                 const cuuint64_t*, const cuuint64_t*, const cuuint32_t*,
                                 const cuuint32_t*, CUtensorMapInterleave, CUtensorMapSwizzle,
                                 CUtensorMapL2promotion, CUtensorMapFloatOOBfill);
    void* fnp = nullptr;
    cudaDriverEntryPointQueryResult qr;
    cudaGetDriverEntryPoint("cuTensorMapEncodeTiled", &fnp, cudaEnableDefault, &qr);
    EncodeFn encode = (EncodeFn)fnp;

    void *wt_ptr, *xp_ptr;
    cudaGetSymbolAddress(&wt_ptr, g_Wt);
    cudaGetSymbolAddress(&xp_ptr, g_xp);

    CUtensorMap tma_a{}, tma_b{};
    {   // A: packed g_Wt as [rows=9216][32 words], 128B rows, linear; box [32, 128]
        cuuint64_t dims[2]    = {32, 9216};
        cuuint64_t strides[1] = {128};
        cuuint32_t box[2]     = {32, 128};
        cuuint32_t es[2]      = {1, 1};
        encode(&tma_a, CU_TENSOR_MAP_DATA_TYPE_FLOAT32, 2, wt_ptr, dims, strides, box, es,
               CU_TENSOR_MAP_INTERLEAVE_NONE, CU_TENSOR_MAP_SWIZZLE_NONE,
               CU_TENSOR_MAP_L2_PROMOTION_L2_128B, CU_TENSOR_MAP_FLOAT_OOB_FILL_NONE);
    }
    {   // B: g_xp [b=32][hp=58][wp=58][c=128]; halo box [32 c, 58 w, 6 h, 1], SW128
        cuuint64_t dims[4]    = {CIN, HP, HP, NB};
        cuuint64_t strides[3] = {CIN * 4, (cuuint64_t)HP * CIN * 4, (cuuint64_t)HP * HP * CIN * 4};
        cuuint32_t box[4]     = {32, 58, 6, 1};
        cuuint32_t es[4]      = {1, 1, 1, 1};
        encode(&tma_b, CU_TENSOR_MAP_DATA_TYPE_FLOAT32, 4, xp_ptr, dims, strides, box, es,
               CU_TENSOR_MAP_INTERLEAVE_NONE, CU_TENSOR_MAP_SWIZZLE_128B,
               CU_TENSOR_MAP_L2_PROMOTION_L2_128B, CU_TENSOR_MAP_FLOAT_OOB_FILL_NONE);
    }

    wt_kernel<<<(COUT * KTOT + 255) / 256, 256>>>(W);
    xpad_kernel<<<NB * HW, 256>>>(x);
    xborder_kernel<<<(NB * 228 * CIN + 255) / 256, 256>>>();

    cudaFuncSetAttribute(conv_tc, cudaFuncAttributeMaxDynamicSharedMemorySize, SMEM_TOTAL);
    dim3 grid(14, 32, 2);
    conv_tc<<<grid, 256, SMEM_TOTAL>>>(tma_a, tma_b, (float*)d_out);
}